// round 14
// baseline (speedup 1.0000x reference)
#include <cuda_runtime.h>
#include <cstddef>

// radiusgraphEdge — N=8192, D=2, L=1.0, R0=0.1, no self-loop.
// Output: [0, N*N) dist (f32, row-major), [N*N, 2*N*N) mask as 0.0/1.0.
//
// R14: Blackwell 256-bit stores. JT=8 per thread with ONE st.global.cs.v8.f32
// per plane-row (32B/lane contiguous -> 1024B/warp contiguous, fully
// coalesced; unlike the R4 JT=8 failure which issued 2x16B at 32B stride).
// Halves store instruction count; IT=2 keeps regs bounded (16 output regs
// per row-pair buffered at store time).
#define NPTS 8192
#define R0_SQ 0.01f
#define THREADS 256
#define IT 2
#define JT 8

__device__ __forceinline__ void stg256_cs(float* p, const float v[8]) {
    asm volatile(
        "st.global.cs.v8.f32 [%0], {%1, %2, %3, %4, %5, %6, %7, %8};"
        :: "l"(p),
           "f"(v[0]), "f"(v[1]), "f"(v[2]), "f"(v[3]),
           "f"(v[4]), "f"(v[5]), "f"(v[6]), "f"(v[7])
        : "memory");
}

__global__ __launch_bounds__(THREADS)
void radius_graph_kernel(const float* __restrict__ x, float* __restrict__ out)
{
    // j fastest in the grid (R5 win): resident CTA wave drains contiguous bands.
    const int j0 = (blockIdx.x * THREADS + threadIdx.x) * JT;
    const int i0 = blockIdx.y * IT;

    // Block-uniform i-points (one 16B broadcast load covers both rows)
    const float4 q01 = *reinterpret_cast<const float4*>(x + 2 * i0);
    const float ix[IT] = {q01.x, q01.z};
    const float iy[IT] = {q01.y, q01.w};

    // 8 consecutive j-points = 64B/lane contiguous (2048B/warp), loaded once
    float px[JT], py[JT];
#pragma unroll
    for (int q = 0; q < JT / 2; ++q) {
        const float4 p = *reinterpret_cast<const float4*>(x + 2 * j0 + 4 * q);
        px[2 * q]     = p.x;  py[2 * q]     = p.y;
        px[2 * q + 1] = p.z;  py[2 * q + 1] = p.w;
    }

#pragma unroll
    for (int m = 0; m < IT; ++m) {
        float dist[JT], mask[JT];
#pragma unroll
        for (int k = 0; k < JT; ++k) {
            float dx = px[k] - ix[m];
            float dy = py[k] - iy[m];
            // Periodic minimum-image, L=1: dr -= round(dr) (rintf = half-even,
            // matching jnp.round)
            dx -= rintf(dx);
            dy -= rintf(dy);
            const float d2 = fmaf(dx, dx, dy * dy);
            float d;
            asm("sqrt.approx.f32 %0, %1;" : "=f"(d) : "f"(d2));
            dist[k] = d;
            mask[k] = (d2 < R0_SQ && (j0 + k) != (i0 + m)) ? 1.0f : 0.0f;
        }

        const size_t base = (size_t)(i0 + m) * NPTS + (size_t)j0;
        // One 256-bit streaming store per plane: 32B/lane, fully coalesced
        stg256_cs(out + base, dist);
        stg256_cs(out + (size_t)NPTS * NPTS + base, mask);
    }
}

extern "C" void kernel_launch(void* const* d_in, const int* in_sizes, int n_in,
                              void* d_out, int out_size)
{
    (void)n_in; (void)in_sizes; (void)out_size;
    const float* x = (const float*)d_in[0];
    float* out = (float*)d_out;

    dim3 grid(NPTS / (THREADS * JT), NPTS / IT);  // (4, 4096): j fastest
    radius_graph_kernel<<<grid, THREADS>>>(x, out);
}

// round 15
// speedup vs baseline: 1.0500x; 1.0500x over previous
#include <cuda_runtime.h>
#include <cstddef>

// radiusgraphEdge — N=8192, D=2, L=1.0, R0=0.1, no self-loop.
// Output: [0, N*N) dist (f32, row-major), [N*N, 2*N*N) mask as 0.0/1.0.
//
// FINAL. Pinned at the HBM write-drain ceiling for the mandatory 537 MB
// output: DRAM 80-82.7% (~6.5 TB/s), invariant across occ 51-80%, regs
// 26-48, i-tile 1-4, j-tile 4/8, block 256/512, .cs/.wt, STG.128/STG.256,
// store order. Wins: j-fastest grid order so the resident CTA wave drains
// contiguous row-bands (-7 us); coalesced 4-wide STG.128 j-tiles; IT=4 load
// amortization; single-MUFU sqrt.approx; mask from d^2 < R0^2. Losses that
// mapped the floor: strided JT=8 (+55 us, broken coalescing), v8 256-bit
// stores (+3.5 us, occupancy drop), .wt (neutral).
#define NPTS 8192
#define R0_SQ 0.01f
#define THREADS 256
#define IT 4

__global__ __launch_bounds__(THREADS)
void radius_graph_kernel(const float* __restrict__ x, float* __restrict__ out)
{
    const int j0 = (blockIdx.x * THREADS + threadIdx.x) * 4;
    const int i0 = blockIdx.y * IT;

    // Block-uniform i-points (two 16B broadcast loads cover 4 rows)
    const float4 q01 = *reinterpret_cast<const float4*>(x + 2 * i0);
    const float4 q23 = *reinterpret_cast<const float4*>(x + 2 * i0 + 4);
    const float ix[IT] = {q01.x, q01.z, q23.x, q23.z};
    const float iy[IT] = {q01.y, q01.w, q23.y, q23.w};

    // Per-thread j-points loaded ONCE, reused for all 4 rows
    const float4 p01 = *reinterpret_cast<const float4*>(x + 2 * j0);
    const float4 p23 = *reinterpret_cast<const float4*>(x + 2 * j0 + 4);
    const float px[4] = {p01.x, p01.z, p23.x, p23.z};
    const float py[4] = {p01.y, p01.w, p23.y, p23.w};

    float4 dist4[IT], mask4[IT];

#pragma unroll
    for (int m = 0; m < IT; ++m) {
        float* dp = &dist4[m].x;
        float* mp = &mask4[m].x;
#pragma unroll
        for (int k = 0; k < 4; ++k) {
            float dx = px[k] - ix[m];
            float dy = py[k] - iy[m];
            // Periodic minimum-image, L=1: dr -= round(dr) (rintf = half-even,
            // matching jnp.round)
            dx -= rintf(dx);
            dy -= rintf(dy);
            const float d2 = fmaf(dx, dx, dy * dy);
            float d;
            asm("sqrt.approx.f32 %0, %1;" : "=f"(d) : "f"(d2));
            dp[k] = d;
            mp[k] = (d2 < R0_SQ && (j0 + k) != (i0 + m)) ? 1.0f : 0.0f;
        }
    }

    // Back-to-back store burst: 4 dist-plane then 4 mask-plane STG.128
    const size_t base0 = (size_t)i0 * NPTS + (size_t)j0;
#pragma unroll
    for (int m = 0; m < IT; ++m)
        __stcs(reinterpret_cast<float4*>(out + base0 + (size_t)m * NPTS), dist4[m]);
#pragma unroll
    for (int m = 0; m < IT; ++m)
        __stcs(reinterpret_cast<float4*>(out + (size_t)NPTS * NPTS + base0 + (size_t)m * NPTS), mask4[m]);
}

extern "C" void kernel_launch(void* const* d_in, const int* in_sizes, int n_in,
                              void* d_out, int out_size)
{
    (void)n_in; (void)in_sizes; (void)out_size;
    const float* x = (const float*)d_in[0];
    float* out = (float*)d_out;

    dim3 grid(NPTS / (THREADS * 4), NPTS / IT);  // (8, 2048): j fastest
    radius_graph_kernel<<<grid, THREADS>>>(x, out);
}